// round 1
// baseline (speedup 1.0000x reference)
#include <cuda_runtime.h>
#include <cuda_bf16.h>

#define N_NODES 10000
#define E_EDGES 160000
#define EP (E_EDGES + N_NODES)   // edges + self loops = 170000
#define IN_CH 128
#define EMB 64
#define HEADS 12
#define HD (HEADS * EMB)          // 768
#define NEG_SLOPE 0.2f

// ---- scratch (device globals; no allocation allowed) ----
__device__ float    g_emb[N_NODES * EMB];      // relu(x@We+be)
__device__ float    g_hh[N_NODES * HD];        // emb@W  [N,12,64]
__device__ float    g_asrc[N_NODES * HEADS];
__device__ float    g_adst[N_NODES * HEADS];
__device__ unsigned g_dmax[N_NODES * HEADS];   // ordered-uint float max
__device__ float    g_denom[N_NODES * HEADS];
__device__ float    g_agg[N_NODES * EMB];      // sum over heads of weighted msgs

// monotone float<->uint map for atomicMax on floats
__device__ __forceinline__ unsigned fkey(float f) {
    unsigned u = __float_as_uint(f);
    return (u & 0x80000000u) ? ~u : (u | 0x80000000u);
}
__device__ __forceinline__ float funkey(unsigned k) {
    unsigned u = (k & 0x80000000u) ? (k & 0x7FFFFFFFu) : ~k;
    return __uint_as_float(u);
}

// ---- pass 1: emb = relu(x @ We + be), 8 nodes per block ----
__global__ void k_emb(const float* __restrict__ x,
                      const float* __restrict__ We,
                      const float* __restrict__ be) {
    __shared__ float sx[IN_CH][8];           // transposed x rows
    int n0 = blockIdx.x * 8;
    int t = threadIdx.x;                     // 0..63
    for (int idx = t; idx < 8 * IN_CH; idx += 64) {
        int i = idx >> 7, k = idx & 127;
        sx[k][i] = x[(n0 + i) * IN_CH + k];
    }
    __syncthreads();
    float acc[8];
    float b = be[t];
#pragma unroll
    for (int i = 0; i < 8; i++) acc[i] = b;
    for (int k = 0; k < IN_CH; k++) {
        float wv = We[k * EMB + t];
#pragma unroll
        for (int i = 0; i < 8; i++) acc[i] += sx[k][i] * wv;
    }
#pragma unroll
    for (int i = 0; i < 8; i++)
        g_emb[(n0 + i) * EMB + t] = fmaxf(acc[i], 0.f);
}

// ---- pass 2: hh = emb @ W  and per-head logits, 8 nodes per block ----
__global__ void k_hh(const float* __restrict__ W,
                     const float* __restrict__ att_src,
                     const float* __restrict__ att_dst) {
    __shared__ float se[EMB][8];             // transposed emb rows
    __shared__ float ssrc[8][HEADS];
    __shared__ float sdst[8][HEADS];
    int n0 = blockIdx.x * 8;
    int t = threadIdx.x;                     // 0..767
    for (int idx = t; idx < 8 * EMB; idx += 768) {
        int i = idx >> 6, k = idx & 63;
        se[k][i] = g_emb[(n0 + i) * EMB + k];
    }
    if (t < 8 * HEADS) {
        ((float*)ssrc)[t] = 0.f;
        ((float*)sdst)[t] = 0.f;
    }
    __syncthreads();
    float acc[8];
#pragma unroll
    for (int i = 0; i < 8; i++) acc[i] = 0.f;
    for (int k = 0; k < EMB; k++) {
        float wv = W[k * HD + t];
#pragma unroll
        for (int i = 0; i < 8; i++) acc[i] += se[k][i] * wv;
    }
    float as = att_src[t], ad = att_dst[t];
    int h = t >> 6;                          // constant within a warp (64 = 2 warps)
#pragma unroll
    for (int i = 0; i < 8; i++) {
        g_hh[(size_t)(n0 + i) * HD + t] = acc[i];
        float ps = acc[i] * as;
        float pd = acc[i] * ad;
#pragma unroll
        for (int off = 16; off; off >>= 1) {
            ps += __shfl_down_sync(0xffffffffu, ps, off);
            pd += __shfl_down_sync(0xffffffffu, pd, off);
        }
        if ((t & 31) == 0) {
            atomicAdd(&ssrc[i][h], ps);
            atomicAdd(&sdst[i][h], pd);
        }
    }
    __syncthreads();
    if (t < 8 * HEADS) {
        int i = t / HEADS, hh_ = t % HEADS;
        g_asrc[(n0 + i) * HEADS + hh_] = ssrc[i][hh_];
        g_adst[(n0 + i) * HEADS + hh_] = sdst[i][hh_];
    }
}

// ---- init scratch each launch (graph replays!) ----
__global__ void k_init() {
    int idx = blockIdx.x * blockDim.x + threadIdx.x;
    if (idx < N_NODES * EMB) g_agg[idx] = 0.f;
    if (idx < N_NODES * HEADS) {
        g_dmax[idx] = 0u;        // minimal key; self-loop always updates
        g_denom[idx] = 0.f;
    }
}

// ---- pass 3a: segment max of leaky-relu logits per (dst, head) ----
__global__ void k_max(const int* __restrict__ ei) {
    int idx = blockIdx.x * blockDim.x + threadIdx.x;
    if (idx >= EP * HEADS) return;
    int e = idx / HEADS, h = idx - e * HEADS;
    int s, d;
    if (e < E_EDGES) { s = ei[e]; d = ei[E_EDGES + e]; }
    else             { s = d = e - E_EDGES; }
    float v = g_asrc[s * HEADS + h] + g_adst[d * HEADS + h];
    v = v > 0.f ? v : NEG_SLOPE * v;
    atomicMax(&g_dmax[d * HEADS + h], fkey(v));
}

// ---- pass 3b: segment sum of exp(e - max) ----
__global__ void k_sum(const int* __restrict__ ei) {
    int idx = blockIdx.x * blockDim.x + threadIdx.x;
    if (idx >= EP * HEADS) return;
    int e = idx / HEADS, h = idx - e * HEADS;
    int s, d;
    if (e < E_EDGES) { s = ei[e]; d = ei[E_EDGES + e]; }
    else             { s = d = e - E_EDGES; }
    float v = g_asrc[s * HEADS + h] + g_adst[d * HEADS + h];
    v = v > 0.f ? v : NEG_SLOPE * v;
    float m = funkey(g_dmax[d * HEADS + h]);
    atomicAdd(&g_denom[d * HEADS + h], expf(v - m));
}

// ---- pass 4: weighted aggregate (head-reduced per edge), 1 warp / edge ----
__global__ void k_agg(const int* __restrict__ ei) {
    int gtid = blockIdx.x * blockDim.x + threadIdx.x;
    int e = gtid >> 5;
    int lane = threadIdx.x & 31;
    if (e >= EP) return;
    int s, d;
    if (e < E_EDGES) { s = ei[e]; d = ei[E_EDGES + e]; }
    else             { s = d = e - E_EDGES; }
    float wlocal = 0.f;
    if (lane < HEADS) {
        float v = g_asrc[s * HEADS + lane] + g_adst[d * HEADS + lane];
        v = v > 0.f ? v : NEG_SLOPE * v;
        float m = funkey(g_dmax[d * HEADS + lane]);
        float den = g_denom[d * HEADS + lane];
        wlocal = expf(v - m) / (den + 1e-16f);
    }
    float w[HEADS];
#pragma unroll
    for (int h = 0; h < HEADS; h++) w[h] = __shfl_sync(0xffffffffu, wlocal, h);
    const float* hrow = g_hh + (size_t)s * HD;
    float m0 = 0.f, m1 = 0.f;
#pragma unroll
    for (int h = 0; h < HEADS; h++) {
        m0 += w[h] * hrow[h * 64 + lane];
        m1 += w[h] * hrow[h * 64 + 32 + lane];
    }
    atomicAdd(&g_agg[d * EMB + lane], m0);
    atomicAdd(&g_agg[d * EMB + 32 + lane], m1);
}

// ---- pass 5: out = relu(emb + mean_heads(agg) + bias) ----
__global__ void k_final(const float* __restrict__ bias, float* __restrict__ out) {
    int idx = blockIdx.x * blockDim.x + threadIdx.x;
    if (idx >= N_NODES * EMB) return;
    int c = idx & 63;
    out[idx] = fmaxf(g_emb[idx] + g_agg[idx] * (1.f / HEADS) + bias[c], 0.f);
}

extern "C" void kernel_launch(void* const* d_in, const int* in_sizes, int n_in,
                              void* d_out, int out_size) {
    const float* x    = (const float*)d_in[0];
    const int*   ei   = (const int*)d_in[1];
    const float* We   = (const float*)d_in[2];
    const float* be   = (const float*)d_in[3];
    const float* W    = (const float*)d_in[4];
    const float* asrc = (const float*)d_in[5];
    const float* adst = (const float*)d_in[6];
    const float* bias = (const float*)d_in[7];
    float* out = (float*)d_out;

    k_emb<<<N_NODES / 8, 64>>>(x, We, be);
    k_init<<<(N_NODES * EMB + 255) / 256, 256>>>();
    k_hh<<<N_NODES / 8, 768>>>(W, asrc, adst);
    k_max<<<(EP * HEADS + 255) / 256, 256>>>(ei);
    k_sum<<<(EP * HEADS + 255) / 256, 256>>>(ei);
    k_agg<<<(EP * 32 + 255) / 256, 256>>>(ei);
    k_final<<<(N_NODES * EMB + 255) / 256, 256>>>(bias, out);
}